// round 7
// baseline (speedup 1.0000x reference)
#include <cuda_runtime.h>
#include <math.h>
#include <float.h>

// ---------------- problem constants ----------------
#define NN        8192      // nodes
#define EE        65536     // edges
#define M1        16
#define DD        4
#define M2        16
#define M2H       48        // 3*M2
#define HS        64        // M2*D
#define NH        4         // attention heads
#define EDGE_DIM  32
#define EHID      64
#define NI        96        // M2H*P
#define NJ        32        // M1*K
#define KROWS     2080      // EHID*NJ + NJ (bias rows appended)
#define EB        128       // edges per CTA in main kernel

// ---------------- device scratch (no allocation allowed) ----------------
__device__ float g_W2p[KROWS * NI];    // repacked weights: [k2][i]
__device__ float g_scores[EE * NH];
__device__ float g_v[EE * HS];
__device__ float g_nmax[NN * NH];
__device__ float g_nsum[NN * NH];
__device__ float g_agg[NN * HS];

// ---------------- helpers ----------------
__device__ __forceinline__ void atomicMaxF(float* addr, float val) {
    int old = __float_as_int(*addr);
    while (__int_as_float(old) < val) {
        int assumed = old;
        old = atomicCAS(reinterpret_cast<int*>(addr), assumed, __float_as_int(val));
        if (old == assumed) break;
    }
}

// ---------------- kernel 0a: repack W2 (+bias) into [k2][i] layout ----------------
// W2p[(c*32+j)*96 + i] = rw_w2[c*3072 + i*32 + j];  rows 2048..2079 hold rw_bias2.
__global__ void k_prep(const float* __restrict__ w2, const float* __restrict__ b2) {
    int idx = blockIdx.x * blockDim.x + threadIdx.x;
    if (idx >= KROWS * NI) return;
    int row = idx / NI;
    int i   = idx - row * NI;
    float v;
    if (row < EHID * NJ) {
        int c = row >> 5, j = row & 31;
        v = w2[c * (NI * NJ) + i * NJ + j];
    } else {
        int j = row - EHID * NJ;
        v = b2[i * NJ + j];
    }
    g_W2p[idx] = v;
}

// ---------------- kernel 0b: reset reductions ----------------
__global__ void k_init() {
    int idx = blockIdx.x * blockDim.x + threadIdx.x;
    if (idx < NN * HS) g_agg[idx] = 0.f;
    if (idx < NN * NH) { g_nmax[idx] = -FLT_MAX; g_nsum[idx] = 0.f; }
}

// ---------------- kernel 1: per-edge heavy compute ----------------
// per CTA: 128 edges. Computes h (edge MLP hidden), t (f_src . basis1),
// then acc[e,i] = sum_{c,j} h[c]*t[j]*W2p[c*32+j, i]  (+ bias rows with h=1),
// then conv = t2 . basis2, attention scores (k.q), v; atomicMax for softmax.
__global__ void __launch_bounds__(EB) k_edge(
    const float* __restrict__ ef, const float* __restrict__ f,
    const float* __restrict__ b1, const float* __restrict__ b2,
    const int*   __restrict__ src_idx, const int* __restrict__ dst_idx,
    const float* __restrict__ w1, const float* __restrict__ bias1)
{
    extern __shared__ float smem[];
    float* h_s  = smem;                       // [64][EB]  (32 KB)
    float* t_s  = smem + EHID * EB;           // [32][EB]  (16 KB)
    float* w_s  = smem + (EHID + NJ) * EB;    // 3072 floats (12 KB)
    float* t2_s = smem;                       // [96][EB] overlays h_s+t_s (48 KB)

    const int tid = threadIdx.x;
    const int e   = blockIdx.x * EB + tid;

    // --- load W1 into shared (reused EB*EHID times) ---
    for (int idx = tid; idx < EDGE_DIM * EHID; idx += EB) w_s[idx] = w1[idx];

    // --- t[j] = sum_d f[src,m,d] * basis1[e,d,k],  j = m*2+k ---
    {
        const int s = src_idx[e];
        float b1r[8];
        #pragma unroll
        for (int z = 0; z < 8; ++z) b1r[z] = b1[e * 8 + z];   // [d][k]
        const float4* frow = reinterpret_cast<const float4*>(f) + s * M1;
        #pragma unroll
        for (int m = 0; m < M1; ++m) {
            float4 fv = frow[m];
            t_s[(2 * m + 0) * EB + tid] = fv.x * b1r[0] + fv.y * b1r[2] + fv.z * b1r[4] + fv.w * b1r[6];
            t_s[(2 * m + 1) * EB + tid] = fv.x * b1r[1] + fv.y * b1r[3] + fv.z * b1r[5] + fv.w * b1r[7];
        }
    }
    __syncthreads();   // W1 in shared ready

    // --- h[c] = relu(ef . W1 + bias1) ---
    {
        float efr[EDGE_DIM];
        #pragma unroll
        for (int x = 0; x < EDGE_DIM; ++x) efr[x] = ef[e * EDGE_DIM + x];
        for (int c = 0; c < EHID; ++c) {
            float s = bias1[c];
            #pragma unroll
            for (int x = 0; x < EDGE_DIM; ++x) s = fmaf(efr[x], w_s[x * EHID + c], s);
            h_s[c * EB + tid] = fmaxf(s, 0.f);
        }
    }

    // --- main GEMM-like loop over 65 c-tiles (last = bias rows, h := 1) ---
    float acc[8][12];
    #pragma unroll
    for (int r = 0; r < 8; ++r)
        #pragma unroll
        for (int ii = 0; ii < 12; ++ii) acc[r][ii] = 0.f;

    const int eg = tid >> 3;        // 0..15 (edge group)
    const int og = tid & 7;         // 0..7  (output group)
    const int ebase = eg * 8;

    for (int ct = 0; ct <= EHID; ++ct) {
        __syncthreads();   // previous w_s tile fully consumed (also covers h/t readiness)
        #pragma unroll 6
        for (int idx = tid; idx < NJ * NI; idx += EB)
            w_s[idx] = g_W2p[ct * (NJ * NI) + idx];
        __syncthreads();

        float hv[8];
        if (ct < EHID) {
            #pragma unroll
            for (int r = 0; r < 8; ++r) hv[r] = h_s[ct * EB + ebase + r];
        } else {
            #pragma unroll
            for (int r = 0; r < 8; ++r) hv[r] = 1.f;
        }

        #pragma unroll 4
        for (int j = 0; j < NJ; ++j) {
            float wv[12];
            #pragma unroll
            for (int ii = 0; ii < 12; ++ii) wv[ii] = w_s[j * NI + og * 12 + ii];
            #pragma unroll
            for (int r = 0; r < 8; ++r) {
                float gt = hv[r] * t_s[j * EB + ebase + r];
                #pragma unroll
                for (int ii = 0; ii < 12; ++ii) acc[r][ii] = fmaf(gt, wv[ii], acc[r][ii]);
            }
        }
    }

    __syncthreads();
    // --- stash t2 = acc into shared, [i][e] layout ---
    #pragma unroll
    for (int r = 0; r < 8; ++r)
        #pragma unroll
        for (int ii = 0; ii < 12; ++ii)
            t2_s[(og * 12 + ii) * EB + ebase + r] = acc[r][ii];
    __syncthreads();

    // --- epilogue: conv = t2 . basis2 ; scores ; v ---
    {
        float b2r[8];
        #pragma unroll
        for (int z = 0; z < 8; ++z) b2r[z] = b2[e * 8 + z];   // [p][d]

        float sc[4] = {0.f, 0.f, 0.f, 0.f};
        #pragma unroll
        for (int o = 0; o < 16; ++o) {
            float a0 = t2_s[(2 * o) * EB + tid],      a1 = t2_s[(2 * o + 1) * EB + tid];
            float q0 = t2_s[(2 * o + 32) * EB + tid], q1 = t2_s[(2 * o + 33) * EB + tid];
            float dot = 0.f;
            #pragma unroll
            for (int d = 0; d < 4; ++d) {
                float kk = a0 * b2r[d] + a1 * b2r[4 + d];
                float qq = q0 * b2r[d] + q1 * b2r[4 + d];
                dot = fmaf(kk, qq, dot);
            }
            sc[o >> 2] += dot;
        }
        #pragma unroll
        for (int o = 0; o < 16; ++o) {
            float a0 = t2_s[(2 * o + 64) * EB + tid], a1 = t2_s[(2 * o + 65) * EB + tid];
            float4 vv;
            vv.x = a0 * b2r[0] + a1 * b2r[4];
            vv.y = a0 * b2r[1] + a1 * b2r[5];
            vv.z = a0 * b2r[2] + a1 * b2r[6];
            vv.w = a0 * b2r[3] + a1 * b2r[7];
            reinterpret_cast<float4*>(g_v)[e * 16 + o] = vv;
        }
        const int dn = dst_idx[e];
        #pragma unroll
        for (int hh = 0; hh < NH; ++hh) {
            float s = sc[hh] * 0.125f;                 // TEMP = HS^-0.5
            s = (s > 0.f) ? s : 0.2f * s;              // leaky_relu(., 0.2)
            g_scores[e * NH + hh] = s;
            atomicMaxF(&g_nmax[dn * NH + hh], s);
        }
    }
}

// ---------------- kernel 2: softmax denominator ----------------
__global__ void k_sum(const int* __restrict__ dst_idx) {
    int idx = blockIdx.x * blockDim.x + threadIdx.x;
    if (idx >= EE * NH) return;
    int e = idx >> 2, hh = idx & 3;
    int dn = dst_idx[e];
    float ex = expf(g_scores[idx] - g_nmax[dn * NH + hh]);
    atomicAdd(&g_nsum[dn * NH + hh], ex);
}

// ---------------- kernel 3: weighted aggregation (copy_e_sum) ----------------
__global__ void k_agg(const int* __restrict__ dst_idx) {
    int idx = blockIdx.x * blockDim.x + threadIdx.x;
    if (idx >= EE * HS) return;
    int e = idx >> 6, x = idx & 63, hh = x >> 4;
    int dn = dst_idx[e];
    float w = expf(g_scores[e * NH + hh] - g_nmax[dn * NH + hh]) / g_nsum[dn * NH + hh];
    atomicAdd(&g_agg[dn * HS + x], w * g_v[idx]);
}

// ---------------- kernel 4: per-irrep equivariant projection ----------------
__global__ void k_proj(const float* __restrict__ pw, const float* __restrict__ pb,
                       float* __restrict__ out) {
    int idx = blockIdx.x * blockDim.x + threadIdx.x;
    if (idx >= NN * HS) return;
    int n  = idx >> 6;
    int m2 = (idx >> 2) & 15;
    int d  = idx & 3;
    int blk = (d == 0) ? 0 : 1;                // IRREP_IDX = [0,1,1,1]
    const float* pwr = pw + (blk * M2 + m2) * M2;
    float s = (d == 0) ? pb[m2] : 0.f;
    #pragma unroll
    for (int m = 0; m < M2; ++m) s = fmaf(pwr[m], g_agg[n * HS + m * 4 + d], s);
    out[idx] = s;
}

// ---------------- launch ----------------
extern "C" void kernel_launch(void* const* d_in, const int* in_sizes, int n_in,
                              void* d_out, int out_size) {
    // setup_inputs() dict order:
    const float* ef    = (const float*)d_in[0];   // edge_feats (E,32)
    const float* f     = (const float*)d_in[1];   // f (N,16,4)
    const float* b1    = (const float*)d_in[2];   // basis1 (E,4,2)
    const float* b2    = (const float*)d_in[3];   // basis2 (E,2,4)
    const int*   src   = (const int*)  d_in[4];   // src_idx (E)
    const int*   dst   = (const int*)  d_in[5];   // dst_idx (E)
    const float* w1    = (const float*)d_in[6];   // rw_w1 (32,64)
    const float* bias1 = (const float*)d_in[7];   // rw_bias1 (64)
    const float* w2    = (const float*)d_in[8];   // rw_w2 (64,3072)
    const float* bias2 = (const float*)d_in[9];   // rw_bias2 (3072)
    const float* pw    = (const float*)d_in[10];  // proj_w (32,16)
    const float* pb    = (const float*)d_in[11];  // proj_b (16,1)
    float* out = (float*)d_out;

    (void)in_sizes; (void)n_in; (void)out_size;

    const int SMEM = (EHID + NJ) * EB * 4 + NJ * NI * 4;  // 61440 B
    cudaFuncSetAttribute(k_edge, cudaFuncAttributeMaxDynamicSharedMemorySize, SMEM);

    k_prep<<<(KROWS * NI + 255) / 256, 256>>>(w2, bias2);
    k_init<<<(NN * HS + 255) / 256, 256>>>();
    k_edge<<<EE / EB, EB, SMEM>>>(ef, f, b1, b2, src, dst, w1, bias1);
    k_sum<<<(EE * NH + 255) / 256, 256>>>(dst);
    k_agg<<<(EE * HS + 255) / 256, 256>>>(dst);
    k_proj<<<(NN * HS + 255) / 256, 256>>>(pw, pb, out);
}

// round 8
// speedup vs baseline: 1.2904x; 1.2904x over previous
#include <cuda_runtime.h>
#include <math.h>
#include <float.h>

// ---------------- problem constants ----------------
#define NN        8192      // nodes
#define EE        65536     // edges
#define M1        16
#define DD        4
#define M2        16
#define M2H       48        // 3*M2
#define HS        64        // M2*D
#define NH        4         // attention heads
#define EDGE_DIM  32
#define EHID      64
#define NI        96        // M2H*P
#define NJ        32        // M1*K
#define KROWS     2080      // EHID*NJ + NJ (bias rows appended)
#define EB        128       // edges per CTA in main kernel

// ---------------- device scratch (no allocation allowed) ----------------
__device__ float g_W2p[KROWS * NI];    // repacked weights: [k2][i]
__device__ float g_scores[EE * NH];
__device__ float g_v[EE * HS];
__device__ float g_nmax[NN * NH];
__device__ float g_nsum[NN * NH];
__device__ float g_agg[NN * HS];

// ---------------- packed fp32x2 helpers (SASS FFMA2 path) ----------------
typedef unsigned long long u64;

__device__ __forceinline__ u64 pack2(float a, float b) {
    u64 r; asm("mov.b64 %0, {%1,%2};" : "=l"(r) : "f"(a), "f"(b)); return r;
}
__device__ __forceinline__ void unpack2(u64 v, float& a, float& b) {
    asm("mov.b64 {%0,%1}, %2;" : "=f"(a), "=f"(b) : "l"(v));
}
__device__ __forceinline__ u64 fma2(u64 a, u64 b, u64 c) {
    u64 d; asm("fma.rn.f32x2 %0, %1, %2, %3;" : "=l"(d) : "l"(a), "l"(b), "l"(c));
    return d;
}

// ---------------- helpers ----------------
__device__ __forceinline__ void atomicMaxF(float* addr, float val) {
    int old = __float_as_int(*addr);
    while (__int_as_float(old) < val) {
        int assumed = old;
        old = atomicCAS(reinterpret_cast<int*>(addr), assumed, __float_as_int(val));
        if (old == assumed) break;
    }
}

// ---------------- kernel 0a: repack W2 (+bias) into [k2][i] layout ----------------
// W2p[(c*32+j)*96 + i] = rw_w2[c*3072 + i*32 + j];  rows 2048..2079 hold rw_bias2.
__global__ void k_prep(const float* __restrict__ w2, const float* __restrict__ b2) {
    int idx = blockIdx.x * blockDim.x + threadIdx.x;
    if (idx >= KROWS * NI) return;
    int row = idx / NI;
    int i   = idx - row * NI;
    float v;
    if (row < EHID * NJ) {
        int c = row >> 5, j = row & 31;
        v = w2[c * (NI * NJ) + i * NJ + j];
    } else {
        int j = row - EHID * NJ;
        v = b2[i * NJ + j];
    }
    g_W2p[idx] = v;
}

// ---------------- kernel 0b: reset reductions ----------------
__global__ void k_init() {
    int idx = blockIdx.x * blockDim.x + threadIdx.x;
    if (idx < NN * HS) g_agg[idx] = 0.f;
    if (idx < NN * NH) { g_nmax[idx] = -FLT_MAX; g_nsum[idx] = 0.f; }
}

// ---------------- kernel 1: per-edge heavy compute ----------------
// per CTA: 128 edges. Computes h (edge MLP hidden), t (f_src . basis1),
// then acc[e,i] = sum_{c,j} h[c]*t[j]*W2p[c*32+j, i]  (+ bias rows with h=1)
// using packed f32x2 FMAs over the output (i) dimension,
// then conv = t2 . basis2, attention scores (k.q), v; atomicMax for softmax.
__global__ void __launch_bounds__(EB) k_edge(
    const float* __restrict__ ef, const float* __restrict__ f,
    const float* __restrict__ b1, const float* __restrict__ b2,
    const int*   __restrict__ src_idx, const int* __restrict__ dst_idx,
    const float* __restrict__ w1, const float* __restrict__ bias1)
{
    extern __shared__ float smem[];
    float* h_s  = smem;                       // [64][EB]  (32 KB)
    float* t_s  = smem + EHID * EB;           // [32][EB]  (16 KB)
    float* w_s  = smem + (EHID + NJ) * EB;    // 3072 floats (12 KB)
    float* t2_s = smem;                       // [96][EB] overlays h_s+t_s (48 KB)

    const int tid = threadIdx.x;
    const int e   = blockIdx.x * EB + tid;

    // --- load W1 into shared (reused EB*EHID times) ---
    for (int idx = tid; idx < EDGE_DIM * EHID; idx += EB) w_s[idx] = w1[idx];

    // --- t[j] = sum_d f[src,m,d] * basis1[e,d,k],  j = m*2+k ---
    {
        const int s = src_idx[e];
        float b1r[8];
        #pragma unroll
        for (int z = 0; z < 8; ++z) b1r[z] = b1[e * 8 + z];   // [d][k]
        const float4* frow = reinterpret_cast<const float4*>(f) + s * M1;
        #pragma unroll
        for (int m = 0; m < M1; ++m) {
            float4 fv = frow[m];
            t_s[(2 * m + 0) * EB + tid] = fv.x * b1r[0] + fv.y * b1r[2] + fv.z * b1r[4] + fv.w * b1r[6];
            t_s[(2 * m + 1) * EB + tid] = fv.x * b1r[1] + fv.y * b1r[3] + fv.z * b1r[5] + fv.w * b1r[7];
        }
    }
    __syncthreads();   // W1 in shared ready

    // --- h[c] = relu(ef . W1 + bias1) ---
    {
        float efr[EDGE_DIM];
        #pragma unroll
        for (int x = 0; x < EDGE_DIM; ++x) efr[x] = ef[e * EDGE_DIM + x];
        for (int c = 0; c < EHID; ++c) {
            float s = bias1[c];
            #pragma unroll
            for (int x = 0; x < EDGE_DIM; ++x) s = fmaf(efr[x], w_s[x * EHID + c], s);
            h_s[c * EB + tid] = fmaxf(s, 0.f);
        }
    }

    // --- main GEMM-like loop over 65 c-tiles (last = bias rows, h := 1) ---
    // acc2[r][p] packs outputs (og*12 + 2p, og*12 + 2p + 1) for edge (ebase+r)
    u64 acc2[8][6];
    #pragma unroll
    for (int r = 0; r < 8; ++r)
        #pragma unroll
        for (int p = 0; p < 6; ++p) acc2[r][p] = 0ULL;

    const int eg = tid >> 3;        // 0..15 (edge group)
    const int og = tid & 7;         // 0..7  (output group)
    const int ebase = eg * 8;

    for (int ct = 0; ct <= EHID; ++ct) {
        __syncthreads();   // previous w_s tile fully consumed (also covers h/t readiness)
        #pragma unroll 6
        for (int idx = tid; idx < NJ * NI; idx += EB)
            w_s[idx] = g_W2p[ct * (NJ * NI) + idx];
        __syncthreads();

        float hv[8];
        if (ct < EHID) {
            float4 h0 = *reinterpret_cast<const float4*>(&h_s[ct * EB + ebase]);
            float4 h1 = *reinterpret_cast<const float4*>(&h_s[ct * EB + ebase + 4]);
            hv[0] = h0.x; hv[1] = h0.y; hv[2] = h0.z; hv[3] = h0.w;
            hv[4] = h1.x; hv[5] = h1.y; hv[6] = h1.z; hv[7] = h1.w;
        } else {
            #pragma unroll
            for (int r = 0; r < 8; ++r) hv[r] = 1.f;
        }

        #pragma unroll 4
        for (int j = 0; j < NJ; ++j) {
            // 12 consecutive weights = 6 packed pairs, loaded as three 16B LDS
            const float* wrow = &w_s[j * NI + og * 12];
            ulonglong2 wa = *reinterpret_cast<const ulonglong2*>(wrow);
            ulonglong2 wb = *reinterpret_cast<const ulonglong2*>(wrow + 4);
            ulonglong2 wc = *reinterpret_cast<const ulonglong2*>(wrow + 8);
            u64 wv2[6] = { wa.x, wa.y, wb.x, wb.y, wc.x, wc.y };

            float4 ta = *reinterpret_cast<const float4*>(&t_s[j * EB + ebase]);
            float4 tb = *reinterpret_cast<const float4*>(&t_s[j * EB + ebase + 4]);
            float tr[8] = { ta.x, ta.y, ta.z, ta.w, tb.x, tb.y, tb.z, tb.w };

            #pragma unroll
            for (int r = 0; r < 8; ++r) {
                float gt = hv[r] * tr[r];
                u64 g2 = pack2(gt, gt);
                #pragma unroll
                for (int p = 0; p < 6; ++p)
                    acc2[r][p] = fma2(g2, wv2[p], acc2[r][p]);
            }
        }
    }

    __syncthreads();
    // --- stash t2 = acc into shared, [i][e] layout ---
    #pragma unroll
    for (int r = 0; r < 8; ++r)
        #pragma unroll
        for (int p = 0; p < 6; ++p) {
            float a, b;
            unpack2(acc2[r][p], a, b);
            t2_s[(og * 12 + 2 * p + 0) * EB + ebase + r] = a;
            t2_s[(og * 12 + 2 * p + 1) * EB + ebase + r] = b;
        }
    __syncthreads();

    // --- epilogue: conv = t2 . basis2 ; scores ; v ---
    {
        float b2r[8];
        #pragma unroll
        for (int z = 0; z < 8; ++z) b2r[z] = b2[e * 8 + z];   // [p][d]

        float sc[4] = {0.f, 0.f, 0.f, 0.f};
        #pragma unroll
        for (int o = 0; o < 16; ++o) {
            float a0 = t2_s[(2 * o) * EB + tid],      a1 = t2_s[(2 * o + 1) * EB + tid];
            float q0 = t2_s[(2 * o + 32) * EB + tid], q1 = t2_s[(2 * o + 33) * EB + tid];
            float dot = 0.f;
            #pragma unroll
            for (int d = 0; d < 4; ++d) {
                float kk = a0 * b2r[d] + a1 * b2r[4 + d];
                float qq = q0 * b2r[d] + q1 * b2r[4 + d];
                dot = fmaf(kk, qq, dot);
            }
            sc[o >> 2] += dot;
        }
        #pragma unroll
        for (int o = 0; o < 16; ++o) {
            float a0 = t2_s[(2 * o + 64) * EB + tid], a1 = t2_s[(2 * o + 65) * EB + tid];
            float4 vv;
            vv.x = a0 * b2r[0] + a1 * b2r[4];
            vv.y = a0 * b2r[1] + a1 * b2r[5];
            vv.z = a0 * b2r[2] + a1 * b2r[6];
            vv.w = a0 * b2r[3] + a1 * b2r[7];
            reinterpret_cast<float4*>(g_v)[e * 16 + o] = vv;
        }
        const int dn = dst_idx[e];
        #pragma unroll
        for (int hh = 0; hh < NH; ++hh) {
            float s = sc[hh] * 0.125f;                 // TEMP = HS^-0.5
            s = (s > 0.f) ? s : 0.2f * s;              // leaky_relu(., 0.2)
            g_scores[e * NH + hh] = s;
            atomicMaxF(&g_nmax[dn * NH + hh], s);
        }
    }
}

// ---------------- kernel 2: softmax denominator ----------------
__global__ void k_sum(const int* __restrict__ dst_idx) {
    int idx = blockIdx.x * blockDim.x + threadIdx.x;
    if (idx >= EE * NH) return;
    int e = idx >> 2, hh = idx & 3;
    int dn = dst_idx[e];
    float ex = expf(g_scores[idx] - g_nmax[dn * NH + hh]);
    atomicAdd(&g_nsum[dn * NH + hh], ex);
}

// ---------------- kernel 3: weighted aggregation (copy_e_sum) ----------------
__global__ void k_agg(const int* __restrict__ dst_idx) {
    int idx = blockIdx.x * blockDim.x + threadIdx.x;
    if (idx >= EE * HS) return;
    int e = idx >> 6, x = idx & 63, hh = x >> 4;
    int dn = dst_idx[e];
    float w = expf(g_scores[e * NH + hh] - g_nmax[dn * NH + hh]) / g_nsum[dn * NH + hh];
    atomicAdd(&g_agg[dn * HS + x], w * g_v[idx]);
}

// ---------------- kernel 4: per-irrep equivariant projection ----------------
__global__ void k_proj(const float* __restrict__ pw, const float* __restrict__ pb,
                       float* __restrict__ out) {
    int idx = blockIdx.x * blockDim.x + threadIdx.x;
    if (idx >= NN * HS) return;
    int n  = idx >> 6;
    int m2 = (idx >> 2) & 15;
    int d  = idx & 3;
    int blk = (d == 0) ? 0 : 1;                // IRREP_IDX = [0,1,1,1]
    const float* pwr = pw + (blk * M2 + m2) * M2;
    float s = (d == 0) ? pb[m2] : 0.f;
    #pragma unroll
    for (int m = 0; m < M2; ++m) s = fmaf(pwr[m], g_agg[n * HS + m * 4 + d], s);
    out[idx] = s;
}

// ---------------- launch ----------------
extern "C" void kernel_launch(void* const* d_in, const int* in_sizes, int n_in,
                              void* d_out, int out_size) {
    // setup_inputs() dict order:
    const float* ef    = (const float*)d_in[0];   // edge_feats (E,32)
    const float* f     = (const float*)d_in[1];   // f (N,16,4)
    const float* b1    = (const float*)d_in[2];   // basis1 (E,4,2)
    const float* b2    = (const float*)d_in[3];   // basis2 (E,2,4)
    const int*   src   = (const int*)  d_in[4];   // src_idx (E)
    const int*   dst   = (const int*)  d_in[5];   // dst_idx (E)
    const float* w1    = (const float*)d_in[6];   // rw_w1 (32,64)
    const float* bias1 = (const float*)d_in[7];   // rw_bias1 (64)
    const float* w2    = (const float*)d_in[8];   // rw_w2 (64,3072)
    const float* bias2 = (const float*)d_in[9];   // rw_bias2 (3072)
    const float* pw    = (const float*)d_in[10];  // proj_w (32,16)
    const float* pb    = (const float*)d_in[11];  // proj_b (16,1)
    float* out = (float*)d_out;

    (void)in_sizes; (void)n_in; (void)out_size;

    const int SMEM = (EHID + NJ) * EB * 4 + NJ * NI * 4;  // 61440 B
    cudaFuncSetAttribute(k_edge, cudaFuncAttributeMaxDynamicSharedMemorySize, SMEM);

    k_prep<<<(KROWS * NI + 255) / 256, 256>>>(w2, bias2);
    k_init<<<(NN * HS + 255) / 256, 256>>>();
    k_edge<<<EE / EB, EB, SMEM>>>(ef, f, b1, b2, src, dst, w1, bias1);
    k_sum<<<(EE * NH + 255) / 256, 256>>>(dst);
    k_agg<<<(EE * HS + 255) / 256, 256>>>(dst);
    k_proj<<<(NN * HS + 255) / 256, 256>>>(pw, pb, out);
}